// round 3
// baseline (speedup 1.0000x reference)
#include <cuda_runtime.h>
#include <cstdint>

// Conv 3x3, pad 1, stride 1.
//   x:       [16, 64, 128, 128]  f32
//   weights: [128, 64, 9]        f32   (taps row-major: (dh,dw) in {0,1,2}^2)
//   out:     [16, 128, 128, 128] f32
//
// Strategy: CUDA-core direct conv using packed fma.rn.f32x2 (FFMA2), which
// doubles fp32 FMA throughput vs scalar FFMA on sm_103a. One CTA per (b,h)
// computes the full 128(O) x 128(W) output row. Accumulators are f32x2 packed
// over adjacent OUTPUT CHANNELS; x values are duplicated into both halves.
// Weights pre-transposed to [tap][c][o] so block loads are coalesced.

#define B_  16
#define C_  64
#define H_  128
#define W_  128
#define O_  128

#define C_CH    16                  // channels per smem chunk
#define N_CH    (C_ / C_CH)         // 4 chunks
#define XS_W    132                 // padded row stride in smem (>=130)
#define WS_ELEMS (9 * C_CH * O_)    // 18432 floats = 72 KB
#define XS_ELEMS (C_CH * 3 * XS_W)  // 6336 floats  = 24.75 KB
#define SMEM_BYTES ((WS_ELEMS + XS_ELEMS) * 4)

// Weight scratch: [tap][c][o]  (9 * 64 * 128 floats = 288 KB)
__device__ float g_wT[9 * C_ * O_];

__global__ void wt_transpose_kernel(const float* __restrict__ w) {
    int i = blockIdx.x * 256 + threadIdx.x;
    if (i < 9 * C_ * O_) {
        int tap = i >> 13;          // / (64*128)
        int rem = i & 8191;
        int c   = rem >> 7;
        int o   = rem & 127;
        g_wT[i] = w[(o * C_ + c) * 9 + tap];
    }
}

__device__ __forceinline__ unsigned long long dup2(float v) {
    unsigned long long r;
    asm("mov.b64 %0, {%1, %1};" : "=l"(r) : "f"(v));
    return r;
}

__device__ __forceinline__ void ffma2(unsigned long long& d,
                                      unsigned long long a,
                                      unsigned long long b) {
    // d = a * b + d   (packed f32x2)
    asm("fma.rn.f32x2 %0, %1, %2, %0;" : "+l"(d) : "l"(a), "l"(b));
}

__global__ __launch_bounds__(256)
void conv3x3_ffma2_kernel(const float* __restrict__ x,
                          float* __restrict__ out) {
    extern __shared__ float sm[];
    float* w_s = sm;                 // [tap][c'][o]  9*16*128
    float* xs  = sm + WS_ELEMS;      // [c'][dh][XS_W]

    const int h   = blockIdx.x;
    const int b   = blockIdx.y;
    const int tid = threadIdx.x;
    const int pw  = tid & 15;        // pixel lane: w = pw + 16*i
    const int po  = tid >> 4;        // channel group: o = po*8 .. po*8+7
    const int o_base = po * 8;

    // 8 pixels x 4 channel-pairs, packed f32x2 accumulators (zero bits == {0,0})
    unsigned long long acc[8][4];
#pragma unroll
    for (int i = 0; i < 8; ++i)
#pragma unroll
        for (int j = 0; j < 4; ++j) acc[i][j] = 0ull;

    for (int cc = 0; cc < N_CH; ++cc) {
        __syncthreads();

        // ---- load weight chunk (coalesced float4 from transposed scratch) ----
        {
            const float4* src = reinterpret_cast<const float4*>(g_wT);
            float4* dst = reinterpret_cast<float4*>(w_s);
            for (int i4 = tid; i4 < WS_ELEMS / 4; i4 += 256) {
                int tap = i4 / (C_CH * 32);                 // 512 f4 per tap
                int r   = i4 - tap * (C_CH * 32);
                int cp  = r >> 5;
                int o4  = r & 31;
                dst[i4] = src[tap * (C_ * 32) + (cc * C_CH + cp) * 32 + o4];
            }
        }

        // ---- load input rows h-1..h+1 for this channel chunk (zero-padded) ----
        {
            for (int i = tid; i < XS_ELEMS; i += 256) {
                int c  = i / (3 * XS_W);
                int r2 = i - c * (3 * XS_W);
                int dh = r2 / XS_W;
                int wi = r2 - dh * XS_W;
                int hi = h + dh - 1;
                int gw = wi - 1;
                float v = 0.0f;
                if (hi >= 0 && hi < H_ && gw >= 0 && gw < W_)
                    v = x[(((b * C_ + cc * C_CH + c) * H_ + hi) << 7) + gw];
                xs[(c * 3 + dh) * XS_W + wi] = v;
            }
        }
        __syncthreads();

        // ---- compute ----
#pragma unroll 1
        for (int c = 0; c < C_CH; ++c) {
#pragma unroll
            for (int dh = 0; dh < 3; ++dh) {
                // weight pairs for taps (dh, 0..2): 8 channels = 2x ulonglong2 each
                unsigned long long w2[3][4];
#pragma unroll
                for (int dw = 0; dw < 3; ++dw) {
                    const ulonglong2* wp = reinterpret_cast<const ulonglong2*>(
                        &w_s[((dh * 3 + dw) * C_CH + c) * O_ + o_base]);
                    ulonglong2 wa = wp[0];
                    ulonglong2 wb = wp[1];
                    w2[dw][0] = wa.x; w2[dw][1] = wa.y;
                    w2[dw][2] = wb.x; w2[dw][3] = wb.y;
                }
                const float* xr = &xs[(c * 3 + dh) * XS_W];
#pragma unroll
                for (int i = 0; i < 8; ++i) {
                    int wi0 = pw + 16 * i;      // padded index for dw=0
                    float a0 = xr[wi0];
                    float a1 = xr[wi0 + 1];
                    float a2 = xr[wi0 + 2];
                    unsigned long long d0 = dup2(a0);
                    unsigned long long d1 = dup2(a1);
                    unsigned long long d2 = dup2(a2);
#pragma unroll
                    for (int j = 0; j < 4; ++j) ffma2(acc[i][j], d0, w2[0][j]);
#pragma unroll
                    for (int j = 0; j < 4; ++j) ffma2(acc[i][j], d1, w2[1][j]);
#pragma unroll
                    for (int j = 0; j < 4; ++j) ffma2(acc[i][j], d2, w2[2][j]);
                }
            }
        }
    }

    // ---- store: out[b][o][h][w] ----
#pragma unroll
    for (int j = 0; j < 4; ++j) {
        int o0 = o_base + 2 * j;
        float* p0 = out + ((b * O_ + o0) * H_ + h) * W_;
        float* p1 = p0 + H_ * W_;      // o0 + 1
#pragma unroll
        for (int i = 0; i < 8; ++i) {
            int w = pw + 16 * i;
            float lo, hi;
            asm("mov.b64 {%0, %1}, %2;" : "=f"(lo), "=f"(hi) : "l"(acc[i][j]));
            p0[w] = lo;
            p1[w] = hi;
        }
    }
}

extern "C" void kernel_launch(void* const* d_in, const int* in_sizes, int n_in,
                              void* d_out, int out_size) {
    const float* x = (const float*)d_in[0];
    const float* w = (const float*)d_in[1];
    float* out = (float*)d_out;

    // Pre-transpose weights into [tap][c][o] scratch (tiny, runs every call —
    // deterministic and graph-capturable).
    wt_transpose_kernel<<<(9 * C_ * O_ + 255) / 256, 256>>>(w);

    cudaFuncSetAttribute(conv3x3_ffma2_kernel,
                         cudaFuncAttributeMaxDynamicSharedMemorySize,
                         SMEM_BYTES);

    dim3 grid(H_, B_);
    conv3x3_ffma2_kernel<<<grid, 256, SMEM_BYTES>>>(x, out);
}

// round 4
// speedup vs baseline: 1.0721x; 1.0721x over previous
#include <cuda_runtime.h>
#include <cstdint>

// Conv 3x3, pad 1, stride 1.
//   x:       [16, 64, 128, 128]  f32
//   weights: [128, 64, 9]        f32
//   out:     [16, 128, 128, 128] f32
//
// R4: contiguous-pixel blocking. Each thread computes 8 CONTIGUOUS pixels x
// 8 output channels using packed fma.rn.f32x2 (channel-pair accumulators).
// Per (c,dh): x comes in as a 12-float window via 3 LDS.128 (was 24 scalar
// LDS), each window value duplicated once into a f32x2 operand (10 dups, was
// 24). Shared-memory crossbar demand drops ~2x below the FMA-pipe demand, so
// the FFMA2 pipe becomes the sole bottleneck. Output is staged through smem
// so global stores stay fully coalesced despite contiguous per-thread pixels.

#define B_  16
#define C_  64
#define H_  128
#define W_  128
#define O_  128

#define C_CH    16                  // channels per smem chunk
#define N_CH    (C_ / C_CH)         // 4 chunks
#define XS_W    132                 // padded row stride (floats); 132*4 % 16 == 0
#define WS_ELEMS (9 * C_CH * O_)    // 18432 floats = 72 KB
#define XS_ELEMS (C_CH * 3 * XS_W)  // 6336 floats  = 24.75 KB
#define SMEM_FLOATS (WS_ELEMS + XS_ELEMS)
#define SMEM_BYTES (SMEM_FLOATS * 4)   // 96.75 KB -> 2 CTAs/SM

// Weight scratch: [tap][c][o]
__device__ float g_wT[9 * C_ * O_];

__global__ void wt_transpose_kernel(const float* __restrict__ w) {
    int i = blockIdx.x * 256 + threadIdx.x;
    if (i < 9 * C_ * O_) {
        int tap = i >> 13;
        int rem = i & 8191;
        int c   = rem >> 7;
        int o   = rem & 127;
        g_wT[i] = w[(o * C_ + c) * 9 + tap];
    }
}

__device__ __forceinline__ unsigned long long dup2(float v) {
    unsigned long long r;
    asm("mov.b64 %0, {%1, %1};" : "=l"(r) : "f"(v));
    return r;
}

__device__ __forceinline__ void ffma2(unsigned long long& d,
                                      unsigned long long a,
                                      unsigned long long b) {
    asm("fma.rn.f32x2 %0, %1, %2, %0;" : "+l"(d) : "l"(a), "l"(b));
}

__global__ __launch_bounds__(256, 2)
void conv3x3_ffma2_kernel(const float* __restrict__ x,
                          float* __restrict__ out) {
    extern __shared__ float sm[];
    float* w_s = sm;                 // [tap][c'][o]
    float* xs  = sm + WS_ELEMS;      // [c'][dh][XS_W]

    const int h   = blockIdx.x;
    const int b   = blockIdx.y;
    const int tid = threadIdx.x;
    const int pw  = tid & 15;        // pixel group: w = pw*8 .. pw*8+7
    const int po  = tid >> 4;        // channel group: o = po*8 .. po*8+7
    const int o_base = po * 8;
    const int wbase  = pw * 8;

    unsigned long long acc[8][4];
#pragma unroll
    for (int i = 0; i < 8; ++i)
#pragma unroll
        for (int j = 0; j < 4; ++j) acc[i][j] = 0ull;

    for (int cc = 0; cc < N_CH; ++cc) {
        __syncthreads();

        // ---- weight chunk: coalesced float4 from transposed scratch ----
        {
            const float4* src = reinterpret_cast<const float4*>(g_wT);
            float4* dst = reinterpret_cast<float4*>(w_s);
            for (int i4 = tid; i4 < WS_ELEMS / 4; i4 += 256) {
                int tap = i4 / (C_CH * 32);
                int r   = i4 - tap * (C_CH * 32);
                int cp  = r >> 5;
                int o4  = r & 31;
                dst[i4] = src[tap * (C_ * 32) + (cc * C_CH + cp) * 32 + o4];
            }
        }

        // ---- input rows h-1..h+1, zero-padded ----
        for (int i = tid; i < XS_ELEMS; i += 256) {
            int c  = i / (3 * XS_W);
            int r2 = i - c * (3 * XS_W);
            int dh = r2 / XS_W;
            int wi = r2 - dh * XS_W;
            int hi = h + dh - 1;
            int gw = wi - 1;
            float v = 0.0f;
            if (hi >= 0 && hi < H_ && gw >= 0 && gw < W_)
                v = x[(((b * C_ + cc * C_CH + c) * H_ + hi) << 7) + gw];
            xs[(c * 3 + dh) * XS_W + wi] = v;
        }
        __syncthreads();

        // ---- compute ----
#pragma unroll 1
        for (int c = 0; c < C_CH; ++c) {
#pragma unroll
            for (int dh = 0; dh < 3; ++dh) {
                // weight pairs for taps (dh,0..2): 6 LDS.128 (broadcast)
                unsigned long long w2[3][4];
#pragma unroll
                for (int dw = 0; dw < 3; ++dw) {
                    const ulonglong2* wp = reinterpret_cast<const ulonglong2*>(
                        &w_s[((dh * 3 + dw) * C_CH + c) * O_ + o_base]);
                    ulonglong2 wa = wp[0];
                    ulonglong2 wb = wp[1];
                    w2[dw][0] = wa.x; w2[dw][1] = wa.y;
                    w2[dw][2] = wb.x; w2[dw][3] = wb.y;
                }
                // 12-float x window via 3 LDS.128 (needs [wbase..wbase+9])
                const float4* xw = reinterpret_cast<const float4*>(
                    &xs[(c * 3 + dh) * XS_W + wbase]);
                float4 xa = xw[0];
                float4 xb = xw[1];
                float4 xc = xw[2];
                unsigned long long d[10];
                d[0] = dup2(xa.x); d[1] = dup2(xa.y);
                d[2] = dup2(xa.z); d[3] = dup2(xa.w);
                d[4] = dup2(xb.x); d[5] = dup2(xb.y);
                d[6] = dup2(xb.z); d[7] = dup2(xb.w);
                d[8] = dup2(xc.x); d[9] = dup2(xc.y);
#pragma unroll
                for (int i = 0; i < 8; ++i) {
#pragma unroll
                    for (int j = 0; j < 4; ++j) ffma2(acc[i][j], d[i],     w2[0][j]);
#pragma unroll
                    for (int j = 0; j < 4; ++j) ffma2(acc[i][j], d[i + 1], w2[1][j]);
#pragma unroll
                    for (int j = 0; j < 4; ++j) ffma2(acc[i][j], d[i + 2], w2[2][j]);
                }
            }
        }
    }

    // ---- epilogue: stage 128x128 tile in smem, then coalesced copy-out ----
    __syncthreads();
    float* stg = sm;   // 16384 floats (64 KB) — reuse chunk buffers
#pragma unroll
    for (int j = 0; j < 4; ++j) {
        int o0 = o_base + 2 * j;
#pragma unroll
        for (int i = 0; i < 8; ++i) {
            float lo, hi;
            asm("mov.b64 {%0, %1}, %2;" : "=f"(lo), "=f"(hi) : "l"(acc[i][j]));
            stg[o0 * W_ + wbase + i]       = lo;
            stg[(o0 + 1) * W_ + wbase + i] = hi;
        }
    }
    __syncthreads();

    const float4* s4 = reinterpret_cast<const float4*>(stg);
    const long obstride = (long)H_ * W_;
    float* obase = out + ((long)b * O_ * H_ + h) * W_;
#pragma unroll
    for (int k = 0; k < 16; ++k) {
        int idx = tid + 256 * k;            // float4 index into 128x128 tile
        float4 v = s4[idx];
        int f = idx << 2;                    // linear float index
        int o = f >> 7;
        int w = f & 127;
        *reinterpret_cast<float4*>(obase + o * obstride + w) = v;
    }
}

extern "C" void kernel_launch(void* const* d_in, const int* in_sizes, int n_in,
                              void* d_out, int out_size) {
    const float* x = (const float*)d_in[0];
    const float* w = (const float*)d_in[1];
    float* out = (float*)d_out;

    wt_transpose_kernel<<<(9 * C_ * O_ + 255) / 256, 256>>>(w);

    cudaFuncSetAttribute(conv3x3_ffma2_kernel,
                         cudaFuncAttributeMaxDynamicSharedMemorySize,
                         SMEM_BYTES);

    dim3 grid(H_, B_);
    conv3x3_ffma2_kernel<<<grid, 256, SMEM_BYTES>>>(x, out);
}

// round 6
// speedup vs baseline: 1.9273x; 1.7978x over previous
#include <cuda_runtime.h>
#include <cuda_bf16.h>
#include <cstdint>

// Conv 3x3 pad1 as implicit GEMM on the legacy tensor path (mma.sync bf16,
// sm_80-baseline instructions -> compiles under plain compute_103).
//   x: [16,64,128,128] f32   w: [128,64,9] f32   out: [16,128,128,128] f32
// 3-pass bf16 split: w = wh+wl, x = xh+xl; out = wh*xh + wh*xl + wl*xh
// accumulated in f32  ->  rel err ~4e-6.
//
// GEMM per CTA (b, 2 h-rows): M=256 pixels, N=128 out-ch, K=16c x 9tap x 4cc.
// A = im2col x [pixel][c16] (dw shift = row offset into 130-row padded tile),
// B = w [tap][o][c16]; both K-contiguous, 48B pitch, non-trans ldmatrix.x4.

#define B_  16
#define C_  64
#define H_  128
#define W_  128
#define O_  128

#define NCC       4
#define KC        16
#define WPITCH    48                       // bytes per 16-ch K row (32 data + 16 pad)
#define W_TAP_SZ  (O_ * WPITCH)            // 6144
#define W_HALF_SZ (9 * W_TAP_SZ)           // 55296
#define W_CC_SZ   (2 * W_HALF_SZ)          // 110592
#define SM_X      W_CC_SZ                  // X tiles after W
#define X_ROW_SZ  (130 * WPITCH)           // 6240
#define X_HALF_SZ (4 * X_ROW_SZ)           // 24960
#define SM_X_LO   (SM_X + X_HALF_SZ)
#define SMEM_TOTAL (SM_X + 2 * X_HALF_SZ)  // 160512
#define STG_PITCH 260                      // f32, output staging pitch

__device__ unsigned char g_W[NCC * W_CC_SZ];   // 442368 B

__global__ void wprep(const float* __restrict__ w) {
    int idx = blockIdx.x * 256 + threadIdx.x;
    if (idx >= NCC * 9 * O_ * KC) return;
    int cc  = idx / (9 * O_ * KC);
    int r   = idx - cc * (9 * O_ * KC);
    int tap = r / (O_ * KC);
    int r2  = r - tap * (O_ * KC);
    int o   = r2 >> 4;
    int c   = r2 & 15;
    float v = w[(o * C_ + cc * KC + c) * 9 + tap];
    __nv_bfloat16 hi = __float2bfloat16_rn(v);
    __nv_bfloat16 lo = __float2bfloat16_rn(v - __bfloat162float(hi));
    size_t base = (size_t)cc * W_CC_SZ + (size_t)tap * W_TAP_SZ + o * WPITCH + c * 2;
    *(__nv_bfloat16*)(g_W + base)             = hi;
    *(__nv_bfloat16*)(g_W + base + W_HALF_SZ) = lo;
}

__device__ __forceinline__ uint32_t smem_u32(const void* p) {
    uint32_t a;
    asm("{ .reg .u64 t; cvta.to.shared.u64 t, %1; cvt.u32.u64 %0, t; }"
        : "=r"(a) : "l"(p));
    return a;
}

__device__ __forceinline__ void ldsm4(uint32_t* r, uint32_t addr) {
    asm volatile("ldmatrix.sync.aligned.m8n8.x4.shared.b16 {%0,%1,%2,%3}, [%4];"
                 : "=r"(r[0]), "=r"(r[1]), "=r"(r[2]), "=r"(r[3]) : "r"(addr));
}

__device__ __forceinline__ void mma16816(float* d, const uint32_t* a,
                                         uint32_t b0, uint32_t b1) {
    asm volatile(
        "mma.sync.aligned.m16n8k16.row.col.f32.bf16.bf16.f32 "
        "{%0,%1,%2,%3}, {%4,%5,%6,%7}, {%8,%9}, {%0,%1,%2,%3};"
        : "+f"(d[0]), "+f"(d[1]), "+f"(d[2]), "+f"(d[3])
        : "r"(a[0]), "r"(a[1]), "r"(a[2]), "r"(a[3]), "r"(b0), "r"(b1));
}

__global__ __launch_bounds__(512, 1)
void conv_mma_kernel(const float* __restrict__ x, float* __restrict__ out) {
    extern __shared__ char smem[];
    const uint32_t smb = smem_u32(smem);
    const int tid = threadIdx.x;
    const int wid = tid >> 5;
    const int lid = tid & 31;
    const int h0  = blockIdx.x * 2;
    const int b   = blockIdx.y;

    const int m_warp = wid & 3;        // 4 m-tiles of 64 pixels (2 per h-row)
    const int n_warp = wid >> 2;       // 4 n-tiles of 32 out-channels
    const int hh     = m_warp >> 1;    // which of the 2 h rows
    const int pm     = (m_warp & 1) * 64;

    float acc[4][4][4];                // [mi][ni][reg]
#pragma unroll
    for (int mi = 0; mi < 4; ++mi)
#pragma unroll
        for (int ni = 0; ni < 4; ++ni)
#pragma unroll
            for (int q = 0; q < 4; ++q) acc[mi][ni][q] = 0.0f;

    const int lrow = lid & 15;
    const int lcol16 = (lid >> 4) * 16;

    for (int cc = 0; cc < NCC; ++cc) {
        __syncthreads();

        // ---- copy pre-split weights (linear float4) ----
        {
            const float4* src = (const float4*)(g_W + (size_t)cc * W_CC_SZ);
            float4* dst = (float4*)smem;
            for (int i = tid; i < W_CC_SZ / 16; i += 512) dst[i] = src[i];
        }

        // ---- build X im2col tiles: 4 rows x 130 pix x 16 c, bf16 hi/lo ----
        for (int i = tid; i < KC * 4 * 130; i += 512) {
            int c    = i / 520;
            int r    = i - c * 520;
            int ridx = r / 130;
            int ps   = r - ridx * 130;
            int hrow = h0 - 1 + ridx;
            int gw   = ps - 1;
            float v = 0.0f;
            if ((unsigned)hrow < H_ && (unsigned)gw < W_)
                v = x[(((b * C_ + cc * KC + c) * H_ + hrow) << 7) + gw];
            __nv_bfloat16 bh = __float2bfloat16_rn(v);
            __nv_bfloat16 bl = __float2bfloat16_rn(v - __bfloat162float(bh));
            int off = ridx * X_ROW_SZ + ps * WPITCH + c * 2;
            *(__nv_bfloat16*)(smem + SM_X + off)             = bh;
            *(__nv_bfloat16*)(smem + SM_X + X_HALF_SZ + off) = bl;
        }
        __syncthreads();

        // ---- compute: 9 k16 steps (dh,dw), 3 passes each ----
        for (int dh = 0; dh < 3; ++dh) {
            const uint32_t xrow_base = smb + SM_X + (hh + dh) * X_ROW_SZ;
            for (int dw = 0; dw < 3; ++dw) {
                const int tap = dh * 3 + dw;

                // B fragments: [half][nb][4]
                uint32_t Bf[2][2][4];
#pragma unroll
                for (int half = 0; half < 2; ++half)
#pragma unroll
                    for (int nb = 0; nb < 2; ++nb) {
                        uint32_t addr = smb + half * W_HALF_SZ + tap * W_TAP_SZ
                                      + (n_warp * 32 + nb * 16 + lrow) * WPITCH
                                      + lcol16;
                        ldsm4(Bf[half][nb], addr);
                    }

                const uint32_t abase = xrow_base + (pm + dw + lrow) * WPITCH + lcol16;
#pragma unroll
                for (int mi = 0; mi < 4; ++mi) {
                    uint32_t Ah[4], Al[4];
                    uint32_t aa = abase + mi * 16 * WPITCH;
                    ldsm4(Ah, aa);
                    ldsm4(Al, aa + X_HALF_SZ);
#pragma unroll
                    for (int ni = 0; ni < 4; ++ni) {
                        int nb = ni >> 1, s = ni & 1;
                        uint32_t bh0 = Bf[0][nb][s], bh1 = Bf[0][nb][s + 2];
                        uint32_t bl0 = Bf[1][nb][s], bl1 = Bf[1][nb][s + 2];
                        mma16816(acc[mi][ni], Ah, bh0, bh1);   // wh*xh
                        mma16816(acc[mi][ni], Al, bh0, bh1);   // wh*xl
                        mma16816(acc[mi][ni], Ah, bl0, bl1);   // wl*xh
                    }
                }
            }
        }
    }

    // ---- epilogue: stage [o][256 gm] f32 (pitch 260), then coalesced out ----
    __syncthreads();
    float* stg = (float*)smem;
#pragma unroll
    for (int mi = 0; mi < 4; ++mi) {
#pragma unroll
        for (int ni = 0; ni < 4; ++ni) {
            int gm = m_warp * 64 + mi * 16 + (lid >> 2);
            int o  = n_warp * 32 + ni * 8 + (lid & 3) * 2;
            stg[o * STG_PITCH + gm]             = acc[mi][ni][0];
            stg[(o + 1) * STG_PITCH + gm]       = acc[mi][ni][1];
            stg[o * STG_PITCH + gm + 8]         = acc[mi][ni][2];
            stg[(o + 1) * STG_PITCH + gm + 8]   = acc[mi][ni][3];
        }
    }
    __syncthreads();

    for (int i = tid; i < 128 * 64; i += 512) {     // 8192 float4
        int o = i >> 6;
        int q = i & 63;
        float4 v = *(const float4*)(stg + o * STG_PITCH + q * 4);
        int gm = q * 4;
        int hhh = gm >> 7;
        int p   = gm & 127;
        *(float4*)(out + (((b * O_ + o) * H_ + h0 + hhh) << 7) + p) = v;
    }
}

extern "C" void kernel_launch(void* const* d_in, const int* in_sizes, int n_in,
                              void* d_out, int out_size) {
    const float* x = (const float*)d_in[0];
    const float* w = (const float*)d_in[1];
    float* out = (float*)d_out;

    wprep<<<(NCC * 9 * O_ * KC + 255) / 256, 256>>>(w);

    cudaFuncSetAttribute(conv_mma_kernel,
                         cudaFuncAttributeMaxDynamicSharedMemorySize, SMEM_TOTAL);
    dim3 grid(H_ / 2, B_);
    conv_mma_kernel<<<grid, 512, SMEM_TOTAL>>>(x, out);
}

// round 8
// speedup vs baseline: 4.0129x; 2.0821x over previous
#include <cuda_runtime.h>
#include <cuda_fp16.h>
#include <cstdint>

// Conv 3x3 pad1 as implicit GEMM, single-pass fp16 mma.sync (f32 accum).
//   x: [16,64,128,128] f32   w: [128,64,9] f32   out: [16,128,128,128] f32
// Expected rel err ~3e-4 (fp16 operand quantization over K=576, f32 accum).
//
// CTA = (b, 2 h rows): GEMM M=256 pixels x N=128 o x K=64c (x9 taps).
// X im2col built once per CTA: [ridx 0..3][ps 0..129][c 0..63] fp16, pitch
// 144 B (conflict-free ldmatrix). Per-tap weight tile (18 KB) streamed with
// cp.async into a double buffer, overlapped with compute.

#define B_  16
#define C_  64
#define H_  128
#define W_  128
#define O_  128

#define WP      144                 // row pitch bytes (128 data + 16 pad)
#define W_TAP   (O_ * WP)           // 18432
#define X_RIDX  (130 * WP)          // 18720
#define SM_W    0                   // 2 tap buffers: 36864
#define SM_X    (2 * W_TAP)         // X: 4 * 18720 = 74880 -> total 111744
#define STG_PITCH 260
#define SMEM_ALLOC 136192           // >= 128*260*4 epilogue staging

__device__ __align__(16) unsigned char g_Wp[9 * W_TAP];   // fp16, padded pitch

__global__ void wprep(const float* __restrict__ w) {
    int idx = blockIdx.x * 256 + threadIdx.x;
    if (idx >= 9 * O_ * C_) return;
    int tap = idx >> 13;             // / 8192
    int r   = idx & 8191;
    int o   = r >> 6;
    int c   = r & 63;
    __half v = __float2half_rn(w[(o * C_ + c) * 9 + tap]);
    *(__half*)(g_Wp + tap * W_TAP + o * WP + c * 2) = v;
}

__device__ __forceinline__ uint32_t smem_u32(const void* p) {
    uint32_t a;
    asm("{ .reg .u64 t; cvta.to.shared.u64 t, %1; cvt.u32.u64 %0, t; }"
        : "=r"(a) : "l"(p));
    return a;
}

__device__ __forceinline__ void cp16(uint32_t d, const void* s) {
    asm volatile("cp.async.cg.shared.global [%0], [%1], 16;"
                 :: "r"(d), "l"(s) : "memory");
}
#define CP_COMMIT() asm volatile("cp.async.commit_group;" ::: "memory")
#define CP_WAIT0()  asm volatile("cp.async.wait_group 0;"  ::: "memory")

__device__ __forceinline__ void ldsm4(uint32_t* r, uint32_t addr) {
    asm volatile("ldmatrix.sync.aligned.m8n8.x4.shared.b16 {%0,%1,%2,%3}, [%4];"
                 : "=r"(r[0]), "=r"(r[1]), "=r"(r[2]), "=r"(r[3]) : "r"(addr));
}

__device__ __forceinline__ void mma16816(float* d, const uint32_t* a,
                                         uint32_t b0, uint32_t b1) {
    asm volatile(
        "mma.sync.aligned.m16n8k16.row.col.f32.f16.f16.f32 "
        "{%0,%1,%2,%3}, {%4,%5,%6,%7}, {%8,%9}, {%0,%1,%2,%3};"
        : "+f"(d[0]), "+f"(d[1]), "+f"(d[2]), "+f"(d[3])
        : "r"(a[0]), "r"(a[1]), "r"(a[2]), "r"(a[3]), "r"(b0), "r"(b1));
}

__global__ __launch_bounds__(512, 1)
void conv_mma_kernel(const float* __restrict__ x, float* __restrict__ out) {
    extern __shared__ char smem[];
    const uint32_t smb = smem_u32(smem);
    const int tid = threadIdx.x;
    const int wid = tid >> 5;
    const int lid = tid & 31;
    const int h0  = blockIdx.x * 2;
    const int b   = blockIdx.y;

    const int m_warp = wid & 3;
    const int n_warp = wid >> 2;
    const int hh     = m_warp >> 1;
    const int pm     = (m_warp & 1) * 64;
    const int lrow   = lid & 15;
    const int lcol16 = (lid >> 4) * 16;

    float acc[4][4][4];
#pragma unroll
    for (int mi = 0; mi < 4; ++mi)
#pragma unroll
        for (int ni = 0; ni < 4; ++ni)
#pragma unroll
            for (int q = 0; q < 4; ++q) acc[mi][ni][q] = 0.0f;

    // ---- prefetch W tap0 into buffer 0 ----
    for (int i = tid; i < W_TAP / 16; i += 512)
        cp16(smb + SM_W + i * 16, g_Wp + i * 16);
    CP_COMMIT();

    // ---- X build (once): interior ps=1..128 via quad-channel STS.64 ----
    // 8192 quads: gw = idx&127, cq = (idx>>7)>>2... rq = idx>>7: cq=rq>>2, ridx=rq&3
    for (int idx = tid; idx < 8192; idx += 512) {
        int gw   = idx & 127;
        int rq   = idx >> 7;
        int cq   = rq >> 2;
        int ridx = rq & 3;
        int hrow = h0 - 1 + ridx;
        float v0 = 0.f, v1 = 0.f, v2 = 0.f, v3 = 0.f;
        if ((unsigned)hrow < H_) {
            const float* base = x + (((b * C_ + cq * 4) * H_ + hrow) << 7) + gw;
            v0 = base[0];
            v1 = base[H_ * W_];
            v2 = base[2 * H_ * W_];
            v3 = base[3 * H_ * W_];
        }
        uint32_t u0, u1;
        {
            __half h0h = __float2half_rn(v0), h1h = __float2half_rn(v1);
            __half h2h = __float2half_rn(v2), h3h = __float2half_rn(v3);
            u0 = (uint32_t)__half_as_ushort(h0h) | ((uint32_t)__half_as_ushort(h1h) << 16);
            u1 = (uint32_t)__half_as_ushort(h2h) | ((uint32_t)__half_as_ushort(h3h) << 16);
        }
        uint32_t addr = smb + SM_X + ridx * X_RIDX + (1 + gw) * WP + cq * 8;
        asm volatile("st.shared.v2.b32 [%0], {%1, %2};"
                     :: "r"(addr), "r"(u0), "r"(u1) : "memory");
    }
    // ---- X edges ps=0, ps=129 -> zero ----
    if (tid < 512) {
        int ridx = tid >> 7;
        int r    = tid & 127;
        int ps   = (r >> 6) * 129;
        int c    = r & 63;
        uint32_t addr = smb + SM_X + ridx * X_RIDX + ps * WP + c * 2;
        asm volatile("st.shared.u16 [%0], %1;" :: "r"(addr), "h"((unsigned short)0) : "memory");
    }

    CP_WAIT0();
    __syncthreads();

    // ---- main loop over 9 taps, streaming W with double buffer ----
    for (int dh = 0; dh < 3; ++dh) {
        for (int dw = 0; dw < 3; ++dw) {
            const int tap = dh * 3 + dw;

            if (tap < 8) {
                const unsigned char* src = g_Wp + (size_t)(tap + 1) * W_TAP;
                uint32_t dst = smb + SM_W + ((tap + 1) & 1) * W_TAP;
                for (int i = tid; i < W_TAP / 16; i += 512)
                    cp16(dst + i * 16, src + i * 16);
            }
            CP_COMMIT();

            const uint32_t wb = smb + SM_W + (tap & 1) * W_TAP;
            const uint32_t xb = smb + SM_X + (hh + dh) * X_RIDX
                              + (pm + dw + lrow) * WP + lcol16;
#pragma unroll
            for (int cc = 0; cc < 4; ++cc) {
                const uint32_t ko = cc * 32;
                uint32_t Bf[2][4];
                ldsm4(Bf[0], wb + (n_warp * 32 + lrow) * WP + ko + lcol16);
                ldsm4(Bf[1], wb + (n_warp * 32 + 16 + lrow) * WP + ko + lcol16);
#pragma unroll
                for (int mi = 0; mi < 4; ++mi) {
                    uint32_t Aa[4];
                    ldsm4(Aa, xb + mi * 16 * WP + ko);
#pragma unroll
                    for (int ni = 0; ni < 4; ++ni) {
                        int nb = ni >> 1, s = ni & 1;
                        mma16816(acc[mi][ni], Aa, Bf[nb][s], Bf[nb][s + 2]);
                    }
                }
            }

            CP_WAIT0();
            __syncthreads();
        }
    }

    // ---- epilogue: stage [o][256 gm] f32 (pitch 260), coalesced copy-out ----
    float* stg = (float*)smem;
#pragma unroll
    for (int mi = 0; mi < 4; ++mi) {
#pragma unroll
        for (int ni = 0; ni < 4; ++ni) {
            int gm = m_warp * 64 + mi * 16 + (lid >> 2);
            int o  = n_warp * 32 + ni * 8 + (lid & 3) * 2;
            stg[o * STG_PITCH + gm]           = acc[mi][ni][0];
            stg[(o + 1) * STG_PITCH + gm]     = acc[mi][ni][1];
            stg[o * STG_PITCH + gm + 8]       = acc[mi][ni][2];
            stg[(o + 1) * STG_PITCH + gm + 8] = acc[mi][ni][3];
        }
    }
    __syncthreads();

    for (int i = tid; i < 128 * 64; i += 512) {
        int o = i >> 6;
        int q = i & 63;
        float4 v = *(const float4*)(stg + o * STG_PITCH + q * 4);
        int gm  = q * 4;
        int hh2 = gm >> 7;
        int p   = gm & 127;
        *(float4*)(out + (((b * O_ + o) * H_ + h0 + hh2) << 7) + p) = v;
    }
}

extern "C" void kernel_launch(void* const* d_in, const int* in_sizes, int n_in,
                              void* d_out, int out_size) {
    const float* x = (const float*)d_in[0];
    const float* w = (const float*)d_in[1];
    float* out = (float*)d_out;

    wprep<<<(9 * O_ * C_ + 255) / 256, 256>>>(w);

    cudaFuncSetAttribute(conv_mma_kernel,
                         cudaFuncAttributeMaxDynamicSharedMemorySize, SMEM_ALLOC);
    dim3 grid(H_ / 2, B_);
    conv_mma_kernel<<<grid, 512, SMEM_ALLOC>>>(x, out);
}

// round 12
// speedup vs baseline: 4.8530x; 1.2093x over previous
#include <cuda_runtime.h>
#include <cuda_fp16.h>
#include <cstdint>

// Conv 3x3 pad1 as implicit GEMM, single-pass fp16 mma.sync (f32 accum).
// R9: all-resident smem (W 147.5K + X 65K via SW128 XOR swizzle, pitch 128B),
// barrier-free 9-tap main loop. CTA = (b, 2 h rows): M=256 pix, N=128 o, K=576.

#define B_  16
#define C_  64
#define H_  128
#define W_  128
#define O_  128

#define W_TAP   16384               // 128 o x 128 B (64 ch fp16), swizzled
#define SM_W    0
#define SM_X    (9 * W_TAP)         // 147456
#define X_RIDX  (130 * 128)         // 16640
#define SMEM_ALLOC (SM_X + 4 * X_RIDX)   // 214016
#define STG_PITCH 260

// fp16 weights, pre-swizzled: [tap][o][chunk^(o&7)][c&7]
__device__ __align__(16) unsigned char g_Wp[9 * W_TAP];

__global__ void wprep(const float* __restrict__ w) {
    int idx = blockIdx.x * 256 + threadIdx.x;
    if (idx >= 9 * O_ * C_) return;
    int tap = idx >> 13;
    int r   = idx & 8191;
    int o   = r >> 6;
    int c   = r & 63;
    __half v = __float2half_rn(w[(o * C_ + c) * 9 + tap]);
    uint32_t off = tap * W_TAP + o * 128 + (((c >> 3) ^ (o & 7)) << 4) + ((c & 7) << 1);
    *(__half*)(g_Wp + off) = v;
}

__device__ __forceinline__ uint32_t smem_u32(const void* p) {
    uint32_t a;
    asm("{ .reg .u64 t; cvta.to.shared.u64 t, %1; cvt.u32.u64 %0, t; }"
        : "=r"(a) : "l"(p));
    return a;
}

__device__ __forceinline__ void cp16(uint32_t d, const void* s) {
    asm volatile("cp.async.cg.shared.global [%0], [%1], 16;"
                 :: "r"(d), "l"(s) : "memory");
}
#define CP_COMMIT() asm volatile("cp.async.commit_group;" ::: "memory")
#define CP_WAIT0()  asm volatile("cp.async.wait_group 0;"  ::: "memory")

__device__ __forceinline__ void ldsm4(uint32_t* r, uint32_t addr) {
    asm volatile("ldmatrix.sync.aligned.m8n8.x4.shared.b16 {%0,%1,%2,%3}, [%4];"
                 : "=r"(r[0]), "=r"(r[1]), "=r"(r[2]), "=r"(r[3]) : "r"(addr));
}

__device__ __forceinline__ void mma16816(float* d, const uint32_t* a,
                                         uint32_t b0, uint32_t b1) {
    asm volatile(
        "mma.sync.aligned.m16n8k16.row.col.f32.f16.f16.f32 "
        "{%0,%1,%2,%3}, {%4,%5,%6,%7}, {%8,%9}, {%0,%1,%2,%3};"
        : "+f"(d[0]), "+f"(d[1]), "+f"(d[2]), "+f"(d[3])
        : "r"(a[0]), "r"(a[1]), "r"(a[2]), "r"(a[3]), "r"(b0), "r"(b1));
}

__global__ __launch_bounds__(512, 1)
void conv_mma_kernel(const float* __restrict__ x, float* __restrict__ out) {
    extern __shared__ char smem[];
    const uint32_t smb = smem_u32(smem);
    const int tid = threadIdx.x;
    const int wid = tid >> 5;
    const int lid = tid & 31;
    const int h0  = blockIdx.x * 2;
    const int b   = blockIdx.y;

    const int m_warp = wid & 3;
    const int n_warp = wid >> 2;
    const int hh     = m_warp >> 1;
    const int pm     = (m_warp & 1) * 64;
    const int lrow   = lid & 15;
    const int hi16   = lid >> 4;          // chunk offset 0/1

    float acc[4][4][4];
#pragma unroll
    for (int mi = 0; mi < 4; ++mi)
#pragma unroll
        for (int ni = 0; ni < 4; ++ni)
#pragma unroll
            for (int q = 0; q < 4; ++q) acc[mi][ni][q] = 0.0f;

    // ---- W: all 9 taps via cp.async (swizzle pre-applied by wprep) ----
    for (int i = tid; i < 9 * W_TAP / 16; i += 512)
        cp16(smb + SM_W + i * 16, g_Wp + i * 16);
    CP_COMMIT();

    // ---- X build: 4 rows x 128 pix x 64 ch, one STS.128 (8 ch) per iter ----
    for (int idx = tid; idx < 4096; idx += 512) {
        int gw   = idx & 127;
        int r    = idx >> 7;
        int cq8  = r >> 2;           // channel octet 0..7
        int ridx = r & 3;
        int hrow = h0 - 1 + ridx;
        float v[8];
#pragma unroll
        for (int j = 0; j < 8; ++j) v[j] = 0.0f;
        if ((unsigned)hrow < H_) {
            const float* base = x + (((b * C_ + cq8 * 8) * H_ + hrow) << 7) + gw;
#pragma unroll
            for (int j = 0; j < 8; ++j) v[j] = base[j * H_ * W_];
        }
        uint32_t u[4];
#pragma unroll
        for (int j = 0; j < 4; ++j) {
            __half a = __float2half_rn(v[2 * j]);
            __half c = __float2half_rn(v[2 * j + 1]);
            u[j] = (uint32_t)__half_as_ushort(a) | ((uint32_t)__half_as_ushort(c) << 16);
        }
        int ps = 1 + gw;
        uint32_t addr = smb + SM_X + ridx * X_RIDX + ps * 128
                      + ((cq8 ^ (ps & 7)) << 4);
        asm volatile("st.shared.v4.b32 [%0], {%1,%2,%3,%4};"
                     :: "r"(addr), "r"(u[0]), "r"(u[1]), "r"(u[2]), "r"(u[3])
                     : "memory");
    }
    // edges ps=0,129 -> zero whole 128B rows
    if (tid < 64) {
        int ridx = tid >> 4;
        int ps   = ((tid >> 3) & 1) * 129;
        int ch   = tid & 7;
        uint32_t addr = smb + SM_X + ridx * X_RIDX + ps * 128 + (ch << 4);
        asm volatile("st.shared.v4.b32 [%0], {%1,%1,%1,%1};"
                     :: "r"(addr), "r"(0u) : "memory");
    }

    CP_WAIT0();
    __syncthreads();

    // ---- main loop: 9 taps x 4 k16-chunks, NO barriers ----
    const uint32_t rowB0 = smb + SM_W + (n_warp * 32 + lrow) * 128;
    const int swB = lrow & 7;
#pragma unroll
    for (int dh = 0; dh < 3; ++dh) {
#pragma unroll
        for (int dw = 0; dw < 3; ++dw) {
            const int tap = dh * 3 + dw;
            const int swA = (dw + lrow) & 7;
            const uint32_t rowA = smb + SM_X + (hh + dh) * X_RIDX
                                + (pm + dw + lrow) * 128;
            const uint32_t rowB = rowB0 + tap * W_TAP;
#pragma unroll
            for (int cc = 0; cc < 4; ++cc) {
                const int lch = cc * 2 + hi16;
                const uint32_t chA = (uint32_t)((lch ^ swA) << 4);
                const uint32_t chB = (uint32_t)((lch ^ swB) << 4);
                uint32_t Bf[2][4];
                ldsm4(Bf[0], rowB + chB);
                ldsm4(Bf[1], rowB + 16 * 128 + chB);
#pragma unroll
                for (int mi = 0; mi < 4; ++mi) {
                    uint32_t Aa[4];
                    ldsm4(Aa, rowA + mi * 2048 + chA);
#pragma unroll
                    for (int ni = 0; ni < 4; ++ni) {
                        int nb = ni >> 1, s = ni & 1;
                        mma16816(acc[mi][ni], Aa, Bf[nb][s], Bf[nb][s + 2]);
                    }
                }
            }
        }
    }

    // ---- epilogue: stage [o][256 gm] f32 (pitch 260), coalesced copy-out ----
    __syncthreads();
    float* stg = (float*)smem;
#pragma unroll
    for (int mi = 0; mi < 4; ++mi) {
#pragma unroll
        for (int ni = 0; ni < 4; ++ni) {
            int gm = m_warp * 64 + mi * 16 + (lid >> 2);
            int o  = n_warp * 32 + ni * 8 + (lid & 3) * 2;
            stg[o * STG_PITCH + gm]           = acc[mi][ni][0];
            stg[(o + 1) * STG_PITCH + gm]     = acc[mi][ni][1];
            stg[o * STG_PITCH + gm + 8]       = acc[mi][ni][2];
            stg[(o + 1) * STG_PITCH + gm + 8] = acc[mi][ni][3];
        }
    }
    __syncthreads();

    for (int i = tid; i < 128 * 64; i += 512) {
        int o = i >> 6;
        int q = i & 63;
        float4 v = *(const float4*)(stg + o * STG_PITCH + q * 4);
        int gm  = q * 4;
        int hh2 = gm >> 7;
        int p   = gm & 127;
        *(float4*)(out + (((b * O_ + o) * H_ + h0 + hh2) << 7) + p) = v;
    }
}

extern "C" void kernel_launch(void* const* d_in, const int* in_sizes, int n_in,
                              void* d_out, int out_size) {
    const float* x = (const float*)d_in[0];
    const float* w = (const float*)d_in[1];
    float* out = (float*)d_out;

    wprep<<<(9 * O_ * C_ + 255) / 256, 256>>>(w);

    cudaFuncSetAttribute(conv_mma_kernel,
                         cudaFuncAttributeMaxDynamicSharedMemorySize, SMEM_ALLOC);
    dim3 grid(H_ / 2, B_);
    conv_mma_kernel<<<grid, 512, SMEM_ALLOC>>>(x, out);
}